// round 5
// baseline (speedup 1.0000x reference)
#include <cuda_runtime.h>
#include <math.h>

#define NLV 16
#define LOG2T 19
#define TMASK ((1u << LOG2T) - 1u)
#define P1 2654435761u
#define P2 805459861u

#define NBUCKET (1 << 18)      // 64^3 Morton buckets
#define MAXN (1 << 20)
#define SCAN_BLOCKS 256        // NBUCKET / 1024

__device__ int g_hist[NBUCKET];     // zero at kernel_launch entry (invariant, restored by scanApply)
__device__ int g_off[NBUCKET];
__device__ int g_bsum[SCAN_BLOCKS];
__device__ float4 g_xs[MAXN];       // sorted coords + original index

struct LP {
    float g[NLV];   // grid = 2/res
    float ig[NLV];  // 1/grid = res/2
};

// ---------- Morton bucketing ----------
__device__ __forceinline__ unsigned spread3(unsigned v) {
    v &= 0x3FF;
    v = (v | (v << 16)) & 0x030000FF;
    v = (v | (v << 8))  & 0x0300F00F;
    v = (v | (v << 4))  & 0x030C30C3;
    v = (v | (v << 2))  & 0x09249249;
    return v;
}

__device__ __forceinline__ unsigned morton_key(const float* __restrict__ x, int n) {
    float px = fminf(fmaxf(x[3 * n + 0], -1.0f), 1.0f) + 1.0f;  // [0,2]
    float py = fminf(fmaxf(x[3 * n + 1], -1.0f), 1.0f) + 1.0f;
    float pz = fminf(fmaxf(x[3 * n + 2], -1.0f), 1.0f) + 1.0f;
    unsigned ix = min(63u, (unsigned)(px * 32.0f));
    unsigned iy = min(63u, (unsigned)(py * 32.0f));
    unsigned iz = min(63u, (unsigned)(pz * 32.0f));
    return (spread3(ix) << 2) | (spread3(iy) << 1) | spread3(iz);
}

__global__ void hist_kernel(const float* __restrict__ x, int N) {
    int n = blockIdx.x * 256 + threadIdx.x;
    if (n >= N) return;
    atomicAdd(&g_hist[morton_key(x, n)], 1);
}

// Block totals of g_hist: 256 blocks x 1024 threads.
__global__ void __launch_bounds__(1024) reduce_kernel() {
    int gid = blockIdx.x * 1024 + threadIdx.x;
    int v = g_hist[gid];
    int lane = threadIdx.x & 31, w = threadIdx.x >> 5;
#pragma unroll
    for (int d = 16; d >= 1; d >>= 1) v += __shfl_down_sync(0xFFFFFFFFu, v, d);
    __shared__ int part[32];
    if (lane == 0) part[w] = v;
    __syncthreads();
    if (w == 0) {
        int t = part[lane];
#pragma unroll
        for (int d = 16; d >= 1; d >>= 1) t += __shfl_down_sync(0xFFFFFFFFu, t, d);
        if (lane == 0) g_bsum[blockIdx.x] = t;
    }
}

// Exclusive scan: each block scans its 1024 elems locally, computes its global
// prefix by summing g_bsum[0..bid) itself (no serial kernel), writes g_off,
// and resets g_hist to zero.
__global__ void __launch_bounds__(1024) scan_apply_kernel() {
    int bid = blockIdx.x;
    int gid = bid * 1024 + threadIdx.x;
    int v = g_hist[gid];
    g_hist[gid] = 0;

    int lane = threadIdx.x & 31, w = threadIdx.x >> 5;

    __shared__ int wsum[32];
    __shared__ int part[8];
    __shared__ int s_pre;

    // block-local inclusive warp scan
    int s = v;
#pragma unroll
    for (int d = 1; d < 32; d <<= 1) {
        int t = __shfl_up_sync(0xFFFFFFFFu, s, d);
        if (lane >= d) s += t;
    }
    if (lane == 31) wsum[w] = s;

    // partial sums of g_bsum[0..bid) using warps 0-7 (threads 0-255)
    if (threadIdx.x < 256) {
        int t = (threadIdx.x < bid) ? g_bsum[threadIdx.x] : 0;
#pragma unroll
        for (int d = 16; d >= 1; d >>= 1) t += __shfl_down_sync(0xFFFFFFFFu, t, d);
        if (lane == 0) part[threadIdx.x >> 5] = t;
    }
    __syncthreads();

    if (w == 0) {
        int t = wsum[lane];
        int ss = t;
#pragma unroll
        for (int d = 1; d < 32; d <<= 1) {
            int u = __shfl_up_sync(0xFFFFFFFFu, ss, d);
            if (lane >= d) ss += u;
        }
        wsum[lane] = ss - t;   // exclusive warp offsets
    }
    if (threadIdx.x == 512) {
        int t = 0;
#pragma unroll
        for (int i = 0; i < 8; i++) t += part[i];
        s_pre = t;
    }
    __syncthreads();

    g_off[gid] = (s - v) + wsum[w] + s_pre;
}

// Scatter: recompute key, claim rank via atomic, stage sorted coords.
__global__ void scatter_kernel(const float* __restrict__ x, int N) {
    int n = blockIdx.x * 256 + threadIdx.x;
    if (n >= N) return;
    unsigned key = morton_key(x, n);
    int pos = atomicAdd(&g_off[key], 1);
    float xx = x[3 * n + 0];
    float xy = x[3 * n + 1];
    float xz = x[3 * n + 2];
    g_xs[pos] = make_float4(xx, xy, xz, __int_as_float(n));
}

// ---------- per-level address/weight computation ----------
__device__ __forceinline__ void level_setup(float px, float py, float pz,
                                            float g, float ig,
                                            unsigned idx[8], float w[8]) {
    int bx = __float2int_rd(px * ig);
    int by = __float2int_rd(py * ig);
    int bz = __float2int_rd(pz * ig);
    float wx = fmaf(-(float)bx, g, px) * ig;
    float wy = fmaf(-(float)by, g, py) * ig;
    float wz = fmaf(-(float)bz, g, pz) * ig;

    unsigned hx0 = (unsigned)bx;
    unsigned hx1 = hx0 + 1u;
    unsigned hy0 = (unsigned)by * P1;
    unsigned hy1 = hy0 + P1;
    unsigned hz0 = (unsigned)bz * P2;
    unsigned hz1 = hz0 + P2;

    unsigned a00 = hx0 ^ hy0;
    unsigned a01 = hx0 ^ hy1;
    unsigned a10 = hx1 ^ hy0;
    unsigned a11 = hx1 ^ hy1;

    idx[0] = (a00 ^ hz0) & TMASK;  // 000
    idx[1] = (a00 ^ hz1) & TMASK;  // 001
    idx[2] = (a01 ^ hz0) & TMASK;  // 010
    idx[3] = (a01 ^ hz1) & TMASK;  // 011
    idx[4] = (a10 ^ hz0) & TMASK;  // 100
    idx[5] = (a10 ^ hz1) & TMASK;  // 101
    idx[6] = (a11 ^ hz0) & TMASK;  // 110
    idx[7] = (a11 ^ hz1) & TMASK;  // 111

    float ux = 1.0f - wx;
    float uy = 1.0f - wy;
    float uz = 1.0f - wz;
    float s00 = uy * uz;
    float s01 = uy * wz;
    float s10 = wy * uz;
    float s11 = wy * wz;
    w[0] = ux * s00; w[1] = ux * s01; w[2] = ux * s10; w[3] = ux * s11;
    w[4] = wx * s00; w[5] = wx * s01; w[6] = wx * s10; w[7] = wx * s11;
}

// ---------- main encoder: level pairs with batched gathers ----------
__global__ void __launch_bounds__(256)
ingp_hash_kernel(const float* __restrict__ x,
                 const float2* __restrict__ emb,
                 float4* __restrict__ out,
                 int N, LP lp, int use_sorted)
{
    int i = blockIdx.x * 256 + threadIdx.x;
    if (i >= N) return;

    int n;
    float xx, xy, xz;
    if (use_sorted) {
        float4 v = g_xs[i];
        xx = v.x; xy = v.y; xz = v.z;
        n = __float_as_int(v.w);
    } else {
        n = i;
        xx = __ldg(x + 3 * n + 0);
        xy = __ldg(x + 3 * n + 1);
        xz = __ldg(x + 3 * n + 2);
    }

    float px = fminf(fmaxf(xx, -1.0f), 1.0f) + 1.0f;
    float py = fminf(fmaxf(xy, -1.0f), 1.0f) + 1.0f;
    float pz = fminf(fmaxf(xz, -1.0f), 1.0f) + 1.0f;

#pragma unroll
    for (int p = 0; p < NLV / 2; p++) {
        int la = 2 * p, lb = 2 * p + 1;
        const float2* __restrict__ ta = emb + ((size_t)la << LOG2T);
        const float2* __restrict__ tb = emb + ((size_t)lb << LOG2T);

        unsigned ia[8], ib[8];
        float wa[8], wb[8];
        level_setup(px, py, pz, lp.g[la], lp.ig[la], ia, wa);
        level_setup(px, py, pz, lp.g[lb], lp.ig[lb], ib, wb);

        float2 ea[8], eb[8];
#pragma unroll
        for (int j = 0; j < 8; j++) ea[j] = __ldg(ta + ia[j]);
#pragma unroll
        for (int j = 0; j < 8; j++) eb[j] = __ldg(tb + ib[j]);

        float rax = wa[0] * ea[0].x;
        float ray = wa[0] * ea[0].y;
#pragma unroll
        for (int j = 1; j < 8; j++) {
            rax = fmaf(wa[j], ea[j].x, rax);
            ray = fmaf(wa[j], ea[j].y, ray);
        }
        float rbx = wb[0] * eb[0].x;
        float rby = wb[0] * eb[0].y;
#pragma unroll
        for (int j = 1; j < 8; j++) {
            rbx = fmaf(wb[j], eb[j].x, rbx);
            rby = fmaf(wb[j], eb[j].y, rby);
        }

        __stcs(out + (size_t)n * 8 + p, make_float4(rax, ray, rbx, rby));
    }
}

extern "C" void kernel_launch(void* const* d_in, const int* in_sizes, int n_in,
                              void* d_out, int out_size)
{
    const float*  x   = (const float*)d_in[0];
    const float2* emb = (const float2*)d_in[1];
    int N = in_sizes[0] / 3;

    LP lp;
    double b = exp((log(512.0) - log(16.0)) / 15.0);
    for (int l = 0; l < NLV; l++) {
        float r = (float)floor(16.0 * pow(b, (double)l));
        lp.g[l]  = 2.0f / r;
        lp.ig[l] = r * 0.5f;
    }

    int blocks = (N + 255) / 256;
    if (blocks <= 0) return;

    if (N <= MAXN) {
        hist_kernel<<<blocks, 256>>>(x, N);
        reduce_kernel<<<SCAN_BLOCKS, 1024>>>();
        scan_apply_kernel<<<SCAN_BLOCKS, 1024>>>();
        scatter_kernel<<<blocks, 256>>>(x, N);
        ingp_hash_kernel<<<blocks, 256>>>(x, emb, (float4*)d_out, N, lp, 1);
    } else {
        ingp_hash_kernel<<<blocks, 256>>>(x, emb, (float4*)d_out, N, lp, 0);
    }
}